// round 3
// baseline (speedup 1.0000x reference)
#include <cuda_runtime.h>
#include <cstdint>

// WeightedRuleLayer: out[r,:] = tanh( sum_p layer_values[idx[r,p],:] * weights[r,p,:] )
// D=128, P=8. One warp per rule, float4 per lane.

#define D_DIM 128
#define PERIOD 8

__device__ int g_idx_is64;

// Detect whether indices buffer is int64 or int32.
// Values are in [0, 200000) so if stored as int64 (little-endian), every odd
// 32-bit word is 0. If stored as int32, odd words are random indices
// (P(all 512 sampled are zero) ~ (1/200000)^512 ~ 0).
__global__ void detect_idx_dtype(const unsigned int* __restrict__ ind_words) {
    unsigned int acc = 0;
    #pragma unroll 8
    for (int i = 0; i < 512; ++i) acc |= ind_words[2 * i + 1];
    g_idx_is64 = (acc == 0u) ? 1 : 0;
}

__global__ __launch_bounds__(256) void weighted_rule_kernel(
    const float* __restrict__ lv,      // [N_SRC, 128]
    const float* __restrict__ w,       // [R, 8, 128]
    const void*  __restrict__ ind,     // [R, 8] int32 or int64
    float* __restrict__ out,           // [R, 128]
    int nrules)
{
    const int warps_per_block = blockDim.x >> 5;
    const int r = blockIdx.x * warps_per_block + (threadIdx.x >> 5);
    if (r >= nrules) return;
    const int lane = threadIdx.x & 31;

    // Load the 8 indices for this rule (uniform across the warp; L1 broadcast).
    long long idx[PERIOD];
    if (g_idx_is64) {
        const long long* p = (const long long*)ind + (size_t)r * PERIOD;
        #pragma unroll
        for (int i = 0; i < PERIOD; ++i) idx[i] = __ldg(p + i);
    } else {
        const int* p = (const int*)ind + (size_t)r * PERIOD;
        #pragma unroll
        for (int i = 0; i < PERIOD; ++i) idx[i] = (long long)__ldg(p + i);
    }

    // Weights: streamed exactly once -> evict-first (.cs) to protect L2 for lv.
    const float4* wp = (const float4*)(w + (size_t)r * PERIOD * D_DIM) + lane;

    float4 acc = make_float4(0.f, 0.f, 0.f, 0.f);
    #pragma unroll
    for (int p = 0; p < PERIOD; ++p) {
        float4 wv = __ldcs(wp + p * 32);
        const float4* xp = (const float4*)(lv + (size_t)idx[p] * D_DIM) + lane;
        float4 xv = __ldg(xp);   // gathered rows: cache normally (L2-resident)
        acc.x = fmaf(wv.x, xv.x, acc.x);
        acc.y = fmaf(wv.y, xv.y, acc.y);
        acc.z = fmaf(wv.z, xv.z, acc.z);
        acc.w = fmaf(wv.w, xv.w, acc.w);
    }

    float4 res;
    res.x = tanhf(acc.x);
    res.y = tanhf(acc.y);
    res.z = tanhf(acc.z);
    res.w = tanhf(acc.w);

    // Output: write-once stream -> evict-first store.
    float4* op = (float4*)(out + (size_t)r * D_DIM) + lane;
    __stcs(op, res);
}

extern "C" void kernel_launch(void* const* d_in, const int* in_sizes, int n_in,
                              void* d_out, int out_size) {
    const float* lv  = (const float*)d_in[0];   // layer_values [200000,128]
    const float* w   = (const float*)d_in[1];   // weights [R,8,128]
    const void*  ind = d_in[2];                 // indices [R,8]

    const int nrules = in_sizes[2] / PERIOD;    // element count regardless of dtype

    detect_idx_dtype<<<1, 1>>>((const unsigned int*)ind);

    const int threads = 256;                    // 8 warps = 8 rules per block
    const int wpb = threads / 32;
    const int blocks = (nrules + wpb - 1) / wpb;
    weighted_rule_kernel<<<blocks, threads>>>(lv, w, ind, (float*)d_out, nrules);
}

// round 7
// speedup vs baseline: 1.0872x; 1.0872x over previous
#include <cuda_runtime.h>
#include <cstdint>

// WeightedRuleLayer: out[r,:] = tanh( sum_p layer_values[idx[r,p],:] * weights[r,p,:] )
// D=128, P=8. One warp per rule, float4 per lane.
//
// Traffic model: weights 1.024GB (stream once, .cs), out 0.128GB (.stcs),
// idx 16MB (.cs), layer_values 102MB with 10x reuse -> pin in L2 (evict_last)
// so the weights stream can't churn it out.

#define D_DIM 128
#define PERIOD 8

__device__ int g_idx_is64;

// Detect int64 vs int32 indices: values < 2e5, so for int64 every odd 32-bit
// word is 0; for int32 odd words are random indices (P all-zero ~ (5e-6)^32 ~ 0).
__global__ void detect_idx_dtype(const unsigned int* __restrict__ ind_words) {
    const int lane = threadIdx.x & 31;
    unsigned int acc = 0;
    #pragma unroll
    for (int i = 0; i < 16; ++i)
        acc |= ind_words[2 * (lane * 16 + i) + 1];
    #pragma unroll
    for (int off = 16; off > 0; off >>= 1)
        acc |= __shfl_xor_sync(0xFFFFFFFFu, acc, off);
    if (lane == 0) g_idx_is64 = (acc == 0u) ? 1 : 0;
}

// L2 evict_last access policy (pin layer_values in L2).
__device__ __forceinline__ unsigned long long policy_evict_last() {
    unsigned long long p;
    asm("createpolicy.fractional.L2::evict_last.b64 %0, 1.0;" : "=l"(p));
    return p;
}

__device__ __forceinline__ float4 ldg_L2_last(const float4* ptr, unsigned long long pol) {
    float4 v;
    asm("ld.global.nc.L2::cache_hint.v4.f32 {%0,%1,%2,%3}, [%4], %5;"
        : "=f"(v.x), "=f"(v.y), "=f"(v.z), "=f"(v.w)
        : "l"(ptr), "l"(pol));
    return v;
}

__global__ __launch_bounds__(256) void weighted_rule_kernel(
    const float* __restrict__ lv,      // [N_SRC, 128] - L2-pinned
    const float* __restrict__ w,       // [R, 8, 128]  - streamed once
    const void*  __restrict__ ind,     // [R, 8] int32 or int64
    float* __restrict__ out,           // [R, 128]     - streamed once
    int nrules)
{
    const int warps_per_block = blockDim.x >> 5;
    const int r = blockIdx.x * warps_per_block + (threadIdx.x >> 5);
    if (r >= nrules) return;
    const int lane = threadIdx.x & 31;

    const unsigned long long pol = policy_evict_last();

    // Indices for this rule (uniform across warp; evict-first, streamed once).
    long long idx[PERIOD];
    if (g_idx_is64) {
        const long long* p = (const long long*)ind + (size_t)r * PERIOD;
        #pragma unroll
        for (int i = 0; i < PERIOD; ++i) idx[i] = __ldcs(p + i);
    } else {
        const int* p = (const int*)ind + (size_t)r * PERIOD;
        #pragma unroll
        for (int i = 0; i < PERIOD; ++i) idx[i] = (long long)__ldcs(p + i);
    }

    const float4* wp = (const float4*)(w + (size_t)r * PERIOD * D_DIM) + lane;

    float4 acc = make_float4(0.f, 0.f, 0.f, 0.f);
    #pragma unroll
    for (int p = 0; p < PERIOD; ++p) {
        float4 wv = __ldcs(wp + p * 32);            // stream, evict-first
        const float4* xp = (const float4*)(lv + (size_t)idx[p] * D_DIM) + lane;
        float4 xv = ldg_L2_last(xp, pol);           // gather, L2-pinned
        acc.x = fmaf(wv.x, xv.x, acc.x);
        acc.y = fmaf(wv.y, xv.y, acc.y);
        acc.z = fmaf(wv.z, xv.z, acc.z);
        acc.w = fmaf(wv.w, xv.w, acc.w);
    }

    float4 res;
    res.x = tanhf(acc.x);
    res.y = tanhf(acc.y);
    res.z = tanhf(acc.z);
    res.w = tanhf(acc.w);

    float4* op = (float4*)(out + (size_t)r * D_DIM) + lane;
    __stcs(op, res);                                // write-once stream
}

extern "C" void kernel_launch(void* const* d_in, const int* in_sizes, int n_in,
                              void* d_out, int out_size) {
    const float* lv  = (const float*)d_in[0];   // layer_values [200000,128]
    const float* w   = (const float*)d_in[1];   // weights [R,8,128]
    const void*  ind = d_in[2];                 // indices [R,8]

    const int nrules = in_sizes[2] / PERIOD;

    detect_idx_dtype<<<1, 32>>>((const unsigned int*)ind);

    const int threads = 256;                    // 8 warps = 8 rules per block
    const int wpb = threads / 32;
    const int blocks = (nrules + wpb - 1) / wpb;
    weighted_rule_kernel<<<blocks, threads>>>(lv, w, ind, (float*)d_out, nrules);
}